// round 14
// baseline (speedup 1.0000x reference)
#include <cuda_runtime.h>
#include <cstdint>

#define VOCAB   32000
#define VWORDS  8000          // VOCAB / 4 (float4 words), < 2^13
#define TPB     512
#define SWORDS  512           // float4 words per stage (8 KB)
#define NSTAGES 16
#define DEPTH   4
#define NBINS   2048
#define QCAP    128           // max gathered quads (-> 512 candidates)
#define MCAP    192           // max compact (element-level) candidates
#define MAXN    4096

typedef unsigned long long u64;
typedef unsigned int       u32;

__device__ int   g_done_ctr = 0;
__device__ float g_Zs[MAXN];
__device__ int   g_qcnts[MAXN];
__device__ u32   g_keys[MAXN][QCAP];

__device__ __forceinline__ u32 f2s(float f) {
    u32 b = __float_as_uint(f);
    return (b & 0x80000000u) ? ~b : (b | 0x80000000u);
}

__device__ __forceinline__ u32 block_scan_u32(u32 v, u32* smem16, int tid) {
    int lane = tid & 31, wid = tid >> 5;
    u32 x = v;
#pragma unroll
    for (int o = 1; o < 32; o <<= 1) {
        u32 t = __shfl_up_sync(0xffffffffu, x, o);
        if (lane >= o) x += t;
    }
    if (lane == 31) smem16[wid] = x;
    __syncthreads();
    if (wid == 0) {
        u32 w = (lane < 16) ? smem16[lane] : 0u;
#pragma unroll
        for (int o = 1; o < 16; o <<= 1) {
            u32 t = __shfl_up_sync(0xffffffffu, w, o);
            if (lane >= o) w += t;
        }
        if (lane < 16) smem16[lane] = w;
    }
    __syncthreads();
    return x + (wid ? smem16[wid - 1] : 0u);
}

// branchless descending top-5 insert; alternate int/float minmax pipes.
__device__ __forceinline__ void ins5(u32 k, u32 (&tv)[5]) {
#pragma unroll
    for (int q = 0; q < 5; q++) {
        if (q & 1) {
            float a = __uint_as_float(tv[q]), b = __uint_as_float(k);
            float hi = fmaxf(a, b), lo = fminf(a, b);
            tv[q] = __float_as_uint(hi); k = __float_as_uint(lo);
        } else {
            u32 hi = max(tv[q], k), lo = min(tv[q], k);
            tv[q] = hi; k = lo;
        }
    }
}

__device__ __forceinline__ float ex2f(float y) {
    float r;
    asm("ex2.approx.f32 %0, %1;" : "=f"(r) : "f"(y));
    return r;
}

__device__ __forceinline__ void proc4(float4 v, int j, float c1,
                                      float& z0, float& z1, float& z2, float& z3,
                                      u32 (&tv)[5]) {
    float e0 = ex2f(v.x * c1), e1 = ex2f(v.y * c1);
    float e2 = ex2f(v.z * c1), e3 = ex2f(v.w * c1);
    z0 += e0; z1 += e1; z2 += e2; z3 += e3;
    float m = fmaxf(fmaxf(e0, e1), fmaxf(e2, e3));
    u32 k = (__float_as_uint(m) & 0xFFFFE000u) | (u32)j;
    ins5(k, tv);
}

// ======== kernel 1: stream + Z + tier-1 gather -> scratch ========
__global__ __launch_bounds__(TPB, 3)
void sampler_stream_kernel(const float* __restrict__ logits,
                           const float* __restrict__ temp_p,
                           const int*   __restrict__ topk_p)
{
    __shared__ float4 s_stage[DEPTH][SWORDS];   // 32 KB
    __shared__ u32    s_hist[NBINS];            // 8 KB
    __shared__ u32    s_t16[16];
    __shared__ float  s_redf[16];
    __shared__ int    s_bin, s_gcnt;

    const int tid  = threadIdx.x;
    const int row  = blockIdx.x;
    const int wid  = tid >> 5;
    const int lane = tid & 31;

    const float invT = 1.0f / (*temp_p);
    const float c1   = 1.44269504088896341f * invT;
    int Kw = *topk_p;
    Kw = max(1, min(Kw, 512));
    const int KQ = min(Kw, QCAP);

    const float* rowp = logits + (size_t)row * VOCAB;
    const float4* rp  = (const float4*)rowp;

    if (tid == 0) s_gcnt = 0;
#pragma unroll
    for (int q = 0; q < NBINS / TPB; q++) s_hist[tid + q * TPB] = 0u;

    u32 tv[5];
#pragma unroll
    for (int q = 0; q < 5; q++) tv[q] = 0u;
    float z0 = 0.f, z1 = 0.f, z2 = 0.f, z3 = 0.f;

    const u32 sbase = (u32)__cvta_generic_to_shared(&s_stage[0][0]) + (u32)tid * 16u;

#define ISSUE(s)                                                              \
    do {                                                                      \
        if ((s) < NSTAGES) {                                                  \
            const int _j = (s) * SWORDS;                                      \
            u32 _dst = sbase + (u32)(((s) & (DEPTH - 1)) * SWORDS * 16);      \
            if ((s) < NSTAGES - 1) {                                          \
                asm volatile("cp.async.cg.shared.global [%0], [%1], 16;"      \
                             :: "r"(_dst), "l"(rp + _j + tid));               \
            } else {                                                          \
                if (_j + tid < VWORDS)                                        \
                    asm volatile("cp.async.cg.shared.global [%0], [%1], 16;"  \
                                 :: "r"(_dst), "l"(rp + _j + tid));           \
            }                                                                 \
        }                                                                     \
        asm volatile("cp.async.commit_group;");                               \
    } while (0)

    ISSUE(0); ISSUE(1); ISSUE(2); ISSUE(3);

#pragma unroll
    for (int s = 0; s < NSTAGES; s++) {
        asm volatile("cp.async.wait_group %0;" :: "n"(DEPTH - 1));
        int j = s * SWORDS + tid;
        if (s < NSTAGES - 1 || j < VWORDS) {
            float4 v = s_stage[s & (DEPTH - 1)][tid];
            proc4(v, j, c1, z0, z1, z2, z3, tv);
        }
        ISSUE(s + DEPTH);
    }
    asm volatile("cp.async.wait_group 0;");

    float zsum = (z0 + z1) + (z2 + z3);
#pragma unroll
    for (int off = 16; off; off >>= 1)
        zsum += __shfl_down_sync(0xffffffffu, zsum, off);
    if (lane == 0) s_redf[wid] = zsum;
    __syncthreads();
    if (tid == 0) {
        float z = 0.0f;
        for (int w = 0; w < 16; w++) z += s_redf[w];
        g_Zs[row] = z;
    }

    // tier-1 histogram of quad keys
#pragma unroll
    for (int q = 0; q < 5; q++)
        atomicAdd(&s_hist[tv[q] >> 21], 1u);
    __syncthreads();

    // suffix scan from highest bin; locate rank-KQ bin
    u32 c4[4]; u32 tsum = 0;
#pragma unroll
    for (int q = 0; q < 4; q++) {
        int bin = (NBINS - 1) - (tid * 4 + q);
        c4[q] = s_hist[bin];
        tsum += c4[q];
    }
    u32 incl = block_scan_u32(tsum, s_t16, tid);
    {
        u32 cum = incl - tsum;
#pragma unroll
        for (int q = 0; q < 4; q++) {
            if (cum < (u32)KQ && cum + c4[q] >= (u32)KQ)
                s_bin = (NBINS - 1) - (tid * 4 + q);
            cum += c4[q];
        }
    }
    __syncthreads();
    const int binSel = s_bin;

    // gather quad keys straight to global scratch
#pragma unroll
    for (int q = 0; q < 5; q++) {
        u32 key = tv[q];
        if ((int)(key >> 21) >= binSel) {
            int pos = atomicAdd(&s_gcnt, 1);
            if (pos < QCAP) g_keys[row][pos] = key;
        }
    }
    __syncthreads();
    if (tid == 0) g_qcnts[row] = min(s_gcnt, QCAP);
}

// ======== kernel 2: per-row epilogue (tier-2 + all-pairs + outputs) ========
__global__ __launch_bounds__(TPB)
void sampler_epilogue_kernel(const float* __restrict__ logits,
                             const float* __restrict__ gumbel,
                             const float* __restrict__ temp_p,
                             const float* __restrict__ topp_p,
                             const int*   __restrict__ topk_p,
                             const float* __restrict__ thr_p,
                             float* __restrict__ out, int N)
{
    __shared__ u32    s_hist[NBINS];            // 8 KB
    __shared__ u64    s_ckey[MCAP];
    __shared__ float  s_cexp[MCAP];
    __shared__ float  s_cx[MCAP];
    __shared__ int    s_cidx[MCAP];
    __shared__ u32    s_t16[16];
    __shared__ u64    s_red64[16];
    __shared__ float  s_redf[16];
    __shared__ int    s_bin, s_cnt2, s_last;

    const int tid  = threadIdx.x;
    const int row  = blockIdx.x;
    const int wid  = tid >> 5;
    const int lane = tid & 31;

    const float invT = 1.0f / (*temp_p);
    const float topP = *topp_p;
    int Kw = *topk_p;
    Kw = max(1, min(Kw, 512));
    const int Ke = min(Kw, 128);

    const float* rowp = logits + (size_t)row * VOCAB;
    const float Z     = g_Zs[row];
    const int   qcnt  = g_qcnts[row];
    const int   gex   = qcnt * 4;

    if (tid == 0) s_cnt2 = 0;
#pragma unroll
    for (int q = 0; q < NBINS / TPB; q++) s_hist[tid + q * TPB] = 0u;

    // expand quads in registers (exact refetch)
    u64 myk = 0ull; float mye = 0.0f, myx = 0.0f; int myidx = 0; u32 mybits = 0;
    if (tid < gex) {
        u32 qk = g_keys[row][tid >> 2];
        myidx = ((int)(qk & 0x1FFFu)) * 4 + (tid & 3);
        myx = __ldg(rowp + myidx) * invT;
        mye = __expf(myx);
        mybits = f2s(myx);
        myk = (((u64)mybits) << 32) | (u32)(VOCAB - myidx);   // tie-break
    }
    __syncthreads();

    if (tid < gex) atomicAdd(&s_hist[mybits >> 21], 1u);
    __syncthreads();

    // suffix scan; locate element rank-Ke bin
    u32 c4[4]; u32 tsum = 0;
#pragma unroll
    for (int q = 0; q < 4; q++) {
        int bin = (NBINS - 1) - (tid * 4 + q);
        c4[q] = s_hist[bin];
        tsum += c4[q];
    }
    u32 incl = block_scan_u32(tsum, s_t16, tid);
    {
        u32 cum = incl - tsum;
#pragma unroll
        for (int q = 0; q < 4; q++) {
            if (cum < (u32)Ke && cum + c4[q] >= (u32)Ke)
                s_bin = (NBINS - 1) - (tid * 4 + q);
            cum += c4[q];
        }
    }
    __syncthreads();
    const int binSel2 = s_bin;

    if (tid < gex && (int)(mybits >> 21) >= binSel2) {
        int pos = atomicAdd(&s_cnt2, 1);
        if (pos < MCAP) {
            s_ckey[pos] = myk;
            s_cexp[pos] = mye;
            s_cx[pos]   = myx;
            s_cidx[pos] = myidx;
        }
    }
    __syncthreads();
    const int mcnt = min(s_cnt2, MCAP);

    // all-pairs rank + prefix over compact set
    float zc = 0.0f; u64 best = 0ull;
    if (tid < mcnt) {
        u64 mk = s_ckey[tid];
        int R = 0; float S = 0.0f;
        for (int j = 0; j < mcnt; j++) {
            u64 kj = s_ckey[j];
            bool gt = kj > mk;
            R += gt ? 1 : 0;
            S += gt ? s_cexp[j] : 0.0f;
        }
        if (R < Kw && S <= topP * Z) {
            zc = s_cexp[tid];
            float g = __ldg(&gumbel[(size_t)row * VOCAB + s_cidx[tid]]);
            best = (((u64)f2s(s_cx[tid] + g)) << 32) | (u32)tid;
        }
    }
#pragma unroll
    for (int off = 16; off; off >>= 1) {
        zc += __shfl_down_sync(0xffffffffu, zc, off);
        u64 o = __shfl_down_sync(0xffffffffu, best, off);
        if (o > best) best = o;
    }
    if (lane == 0) { s_redf[wid] = zc; s_red64[wid] = best; }
    __syncthreads();
    if (tid == 0) {
        float Zp = 0.0f; u64 b = 0ull;
        for (int w = 0; w < 16; w++) {
            Zp += s_redf[w];
            if (s_red64[w] > b) b = s_red64[w];
        }
        int sel = (int)(u32)b;
        float conf = s_cexp[sel] / Zp;
        out[row]         = conf;
        out[N + row]     = (float)s_cidx[sel];
        out[2 * N + row] = conf;

        __threadfence();
        int prev = atomicAdd(&g_done_ctr, 1);
        s_last = (prev == N - 1) ? 1 : 0;
    }
    __syncthreads();

    // last block: cross-row finalize (accepted flags)
    if (s_last) {
        __threadfence();
        const float thr = *thr_p;
        u64 fb = 0ull; int anyl = 0;
        float cv[4];
#pragma unroll
        for (int q = 0; q < 4; q++) {
            int r = tid + q * TPB;
            float c = (r < N) ? out[r] : -1.0f;
            cv[q] = c;
            if (r < N) {
                if (c > thr) anyl = 1;
                u64 k = (((u64)f2s(c)) << 32) | (u32)(N - 1 - r);
                if (k > fb) fb = k;
            }
        }
#pragma unroll
        for (int off = 16; off; off >>= 1) {
            u64 o = __shfl_down_sync(0xffffffffu, fb, off);
            if (o > fb) fb = o;
        }
        int anyw = __any_sync(0xffffffffu, anyl);
        if (lane == 0) { s_red64[wid] = fb; s_t16[wid] = (u32)anyw; }
        __syncthreads();
        if (tid == 0) {
            u64 b = 0ull; u32 a = 0;
            for (int w = 0; w < 16; w++) {
                if (s_red64[w] > b) b = s_red64[w];
                a |= s_t16[w];
            }
            s_red64[0] = b;
            s_t16[0] = a;
            g_done_ctr = 0;
        }
        __syncthreads();
        const int argrow = N - 1 - (int)(u32)s_red64[0];
        const int anyh = (int)s_t16[0];
#pragma unroll
        for (int q = 0; q < 4; q++) {
            int r = tid + q * TPB;
            if (r < N)
                out[3 * N + r] = anyh ? ((cv[q] > thr) ? 1.0f : 0.0f)
                                      : ((r == argrow) ? 1.0f : 0.0f);
        }
    }
}

extern "C" void kernel_launch(void* const* d_in, const int* in_sizes, int n_in,
                              void* d_out, int out_size)
{
    const float* logits = (const float*)d_in[0];
    const float* gumbel = (const float*)d_in[1];
    const float* temp   = (const float*)d_in[2];
    const float* topp   = (const float*)d_in[3];
    const int*   topk   = (const int*)  d_in[4];
    const float* thr    = (const float*)d_in[5];

    int N = in_sizes[0] / VOCAB;
    float* out = (float*)d_out;

    sampler_stream_kernel<<<N, TPB>>>(logits, temp, topk);
    sampler_epilogue_kernel<<<N, TPB>>>(logits, gumbel, temp, topp, topk, thr, out, N);
}

// round 15
// speedup vs baseline: 1.2082x; 1.2082x over previous
#include <cuda_runtime.h>
#include <cstdint>

#define VOCAB   32000
#define VWORDS  8000          // VOCAB / 4 (float4 words), < 2^13
#define TPB     512
#define SWORDS  512           // float4 words per stage (8 KB)
#define NSTAGES 16
#define DEPTH   4
#define NBINS   2048
#define QCAP    128           // max gathered quads (-> 512 candidates)
#define MCAP    192           // max compact (element-level) candidates
#define GRIDP   444           // persistent grid (148 SMs x 3 blocks)

typedef unsigned long long u64;
typedef unsigned int       u32;

__device__ int g_done_ctr = 0;

__device__ __forceinline__ u32 f2s(float f) {
    u32 b = __float_as_uint(f);
    return (b & 0x80000000u) ? ~b : (b | 0x80000000u);
}

__device__ __forceinline__ u32 block_scan_u32(u32 v, u32* smem16, int tid) {
    int lane = tid & 31, wid = tid >> 5;
    u32 x = v;
#pragma unroll
    for (int o = 1; o < 32; o <<= 1) {
        u32 t = __shfl_up_sync(0xffffffffu, x, o);
        if (lane >= o) x += t;
    }
    if (lane == 31) smem16[wid] = x;
    __syncthreads();
    if (wid == 0) {
        u32 w = (lane < 16) ? smem16[lane] : 0u;
#pragma unroll
        for (int o = 1; o < 16; o <<= 1) {
            u32 t = __shfl_up_sync(0xffffffffu, w, o);
            if (lane >= o) w += t;
        }
        if (lane < 16) smem16[lane] = w;
    }
    __syncthreads();
    return x + (wid ? smem16[wid - 1] : 0u);
}

// branchless descending top-5 insert; alternate int/float minmax pipes.
__device__ __forceinline__ void ins5(u32 k, u32 (&tv)[5]) {
#pragma unroll
    for (int q = 0; q < 5; q++) {
        if (q & 1) {
            float a = __uint_as_float(tv[q]), b = __uint_as_float(k);
            float hi = fmaxf(a, b), lo = fminf(a, b);
            tv[q] = __float_as_uint(hi); k = __float_as_uint(lo);
        } else {
            u32 hi = max(tv[q], k), lo = min(tv[q], k);
            tv[q] = hi; k = lo;
        }
    }
}

__device__ __forceinline__ float ex2f(float y) {
    float r;
    asm("ex2.approx.f32 %0, %1;" : "=f"(r) : "f"(y));
    return r;
}

__device__ __forceinline__ void proc4(float4 v, int j, float c1,
                                      float& z0, float& z1, float& z2, float& z3,
                                      u32 (&tv)[5]) {
    float e0 = ex2f(v.x * c1), e1 = ex2f(v.y * c1);
    float e2 = ex2f(v.z * c1), e3 = ex2f(v.w * c1);
    z0 += e0; z1 += e1; z2 += e2; z3 += e3;
    float m = fmaxf(fmaxf(e0, e1), fmaxf(e2, e3));
    u32 k = (__float_as_uint(m) & 0xFFFFE000u) | (u32)j;
    ins5(k, tv);
}

__global__ __launch_bounds__(TPB, 3)
void sampler_row_kernel(const float* __restrict__ logits,
                        const float* __restrict__ gumbel,
                        const float* __restrict__ temp_p,
                        const float* __restrict__ topp_p,
                        const int*   __restrict__ topk_p,
                        const float* __restrict__ thr_p,
                        float* __restrict__ out, int N)
{
    __shared__ float4 s_stage[DEPTH][SWORDS];   // 32 KB (mainloop only)
    __shared__ u32    s_hist[NBINS];            // 8 KB (reused for both tiers)
    __shared__ u32    s_g32[QCAP];
    __shared__ u64    s_ckey[MCAP];
    __shared__ float  s_cexp[MCAP];
    __shared__ float  s_cx[MCAP];
    __shared__ int    s_cidx[MCAP];
    __shared__ u32    s_t16[16];
    __shared__ u64    s_red64[16];
    __shared__ float  s_redf[16];
    __shared__ int    s_bin, s_gcnt, s_cnt2, s_last;

    const int tid  = threadIdx.x;
    const int wid  = tid >> 5;
    const int lane = tid & 31;
    const int G    = gridDim.x;

    const float invT = 1.0f / (*temp_p);
    const float c1   = 1.44269504088896341f * invT;
    const float topP = *topp_p;
    int Kw = *topk_p;
    Kw = max(1, min(Kw, 512));
    const int KQ = min(Kw, QCAP);
    const int Ke = min(Kw, 128);

    const u32 sbase = (u32)__cvta_generic_to_shared(&s_stage[0][0]) + (u32)tid * 16u;

#define ISSUE_FULL(ptr, s)                                                    \
    do {                                                                      \
        u32 _dst = sbase + (u32)(((s) & (DEPTH - 1)) * SWORDS * 16);          \
        asm volatile("cp.async.cg.shared.global [%0], [%1], 16;"              \
                     :: "r"(_dst), "l"((ptr) + (s) * SWORDS + tid));          \
        asm volatile("cp.async.commit_group;");                               \
    } while (0)

#define ISSUE_TAIL(ptr, s)                                                    \
    do {                                                                      \
        u32 _dst = sbase + (u32)(((s) & (DEPTH - 1)) * SWORDS * 16);          \
        if ((s) * SWORDS + tid < VWORDS)                                      \
            asm volatile("cp.async.cg.shared.global [%0], [%1], 16;"          \
                         :: "r"(_dst), "l"((ptr) + (s) * SWORDS + tid));      \
        asm volatile("cp.async.commit_group;");                               \
    } while (0)

#define COMMIT_EMPTY() asm volatile("cp.async.commit_group;")

    // prologue: prefetch first row's stages 0..3
    if (blockIdx.x < N) {
        const float4* rp0 = (const float4*)(logits + (size_t)blockIdx.x * VOCAB);
        ISSUE_FULL(rp0, 0); ISSUE_FULL(rp0, 1);
        ISSUE_FULL(rp0, 2); ISSUE_FULL(rp0, 3);
    }

    for (int row = blockIdx.x; row < N; row += G) {
        const float* rowp = logits + (size_t)row * VOCAB;
        const float4* rp  = (const float4*)rowp;
        const bool hasnext = (row + G) < N;
        const float4* rpn = hasnext
            ? (const float4*)(logits + (size_t)(row + G) * VOCAB) : rp;

        if (tid == 0) { s_gcnt = 0; s_cnt2 = 0; }
#pragma unroll
        for (int q = 0; q < NBINS / TPB; q++) s_hist[tid + q * TPB] = 0u;

        u32 tv[5];
#pragma unroll
        for (int q = 0; q < 5; q++) tv[q] = 0u;
        float z0 = 0.f, z1 = 0.f, z2 = 0.f, z3 = 0.f;

#pragma unroll
        for (int s = 0; s < NSTAGES; s++) {
            asm volatile("cp.async.wait_group %0;" :: "n"(DEPTH - 1));
            int j = s * SWORDS + tid;
            if (s < NSTAGES - 1 || j < VWORDS) {
                float4 v = s_stage[s & (DEPTH - 1)][tid];
                proc4(v, j, c1, z0, z1, z2, z3, tv);
            }
            // issue lookahead: current row stages 4..15, then next row 0..3
            if (s < NSTAGES - DEPTH) {
                if (s + DEPTH < NSTAGES - 1) ISSUE_FULL(rp, s + DEPTH);
                else                         ISSUE_TAIL(rp, NSTAGES - 1);
            } else {
                if (hasnext) ISSUE_FULL(rpn, s - (NSTAGES - DEPTH));
                else         COMMIT_EMPTY();
            }
        }
        // pending groups now = next row's stages 0..3 (completing during epilogue)

        float zsum = (z0 + z1) + (z2 + z3);
#pragma unroll
        for (int off = 16; off; off >>= 1)
            zsum += __shfl_down_sync(0xffffffffu, zsum, off);
        if (lane == 0) s_redf[wid] = zsum;
        __syncthreads();
        float Z;
        if (tid == 0) {
            float z = 0.0f;
            for (int w = 0; w < 16; w++) z += s_redf[w];
            s_redf[0] = z;
        }

        // tier-1 histogram of quad keys
#pragma unroll
        for (int q = 0; q < 5; q++)
            atomicAdd(&s_hist[tv[q] >> 21], 1u);
        __syncthreads();
        Z = s_redf[0];

        // suffix scan from highest bin; locate rank-KQ bin
        u32 c4[4]; u32 tsum = 0;
#pragma unroll
        for (int q = 0; q < 4; q++) {
            int bin = (NBINS - 1) - (tid * 4 + q);
            c4[q] = s_hist[bin];
            tsum += c4[q];
        }
        u32 incl = block_scan_u32(tsum, s_t16, tid);
        {
            u32 cum = incl - tsum;
#pragma unroll
            for (int q = 0; q < 4; q++) {
                if (cum < (u32)KQ && cum + c4[q] >= (u32)KQ)
                    s_bin = (NBINS - 1) - (tid * 4 + q);
                cum += c4[q];
            }
        }
        __syncthreads();
        const int binSel = s_bin;

        // gather quad keys in bins >= binSel
#pragma unroll
        for (int q = 0; q < 5; q++) {
            u32 key = tv[q];
            if ((int)(key >> 21) >= binSel) {
                int pos = atomicAdd(&s_gcnt, 1);
                if (pos < QCAP) s_g32[pos] = key;
            }
        }
        __syncthreads();
        const int qcnt = min(s_gcnt, QCAP);
        const int gex  = qcnt * 4;

        // tier 2: expand quads; element-level cutoff
        u64 myk = 0ull; float mye = 0.0f, myx = 0.0f; int myidx = 0; u32 mybits = 0;
        if (tid < gex) {
            u32 qk = s_g32[tid >> 2];
            myidx = ((int)(qk & 0x1FFFu)) * 4 + (tid & 3);
            myx = __ldg(rowp + myidx) * invT;
            mye = __expf(myx);
            mybits = f2s(myx);
            myk = (((u64)mybits) << 32) | (u32)(VOCAB - myidx);
        }
#pragma unroll
        for (int q = 0; q < NBINS / TPB; q++) s_hist[tid + q * TPB] = 0u;
        __syncthreads();

        if (tid < gex) atomicAdd(&s_hist[mybits >> 21], 1u);
        __syncthreads();

        tsum = 0;
#pragma unroll
        for (int q = 0; q < 4; q++) {
            int bin = (NBINS - 1) - (tid * 4 + q);
            c4[q] = s_hist[bin];
            tsum += c4[q];
        }
        incl = block_scan_u32(tsum, s_t16, tid);
        {
            u32 cum = incl - tsum;
#pragma unroll
            for (int q = 0; q < 4; q++) {
                if (cum < (u32)Ke && cum + c4[q] >= (u32)Ke)
                    s_bin = (NBINS - 1) - (tid * 4 + q);
                cum += c4[q];
            }
        }
        __syncthreads();
        const int binSel2 = s_bin;

        if (tid < gex && (int)(mybits >> 21) >= binSel2) {
            int pos = atomicAdd(&s_cnt2, 1);
            if (pos < MCAP) {
                s_ckey[pos] = myk;
                s_cexp[pos] = mye;
                s_cx[pos]   = myx;
                s_cidx[pos] = myidx;
            }
        }
        __syncthreads();
        const int mcnt = min(s_cnt2, MCAP);

        // all-pairs rank + prefix over compact set
        float zc = 0.0f; u64 best = 0ull;
        if (tid < mcnt) {
            u64 mk = s_ckey[tid];
            int R = 0; float S = 0.0f;
            for (int j = 0; j < mcnt; j++) {
                u64 kj = s_ckey[j];
                bool gt = kj > mk;
                R += gt ? 1 : 0;
                S += gt ? s_cexp[j] : 0.0f;
            }
            if (R < Kw && S <= topP * Z) {
                zc = s_cexp[tid];
                float g = __ldg(&gumbel[(size_t)row * VOCAB + s_cidx[tid]]);
                best = (((u64)f2s(s_cx[tid] + g)) << 32) | (u32)tid;
            }
        }
#pragma unroll
        for (int off = 16; off; off >>= 1) {
            zc += __shfl_down_sync(0xffffffffu, zc, off);
            u64 o = __shfl_down_sync(0xffffffffu, best, off);
            if (o > best) best = o;
        }
        if (lane == 0) { s_redf[wid] = zc; s_red64[wid] = best; }
        __syncthreads();
        if (tid == 0) {
            float Zp = 0.0f; u64 b = 0ull;
            for (int w = 0; w < 16; w++) {
                Zp += s_redf[w];
                if (s_red64[w] > b) b = s_red64[w];
            }
            int sel = (int)(u32)b;
            float conf = s_cexp[sel] / Zp;
            out[row]         = conf;
            out[N + row]     = (float)s_cidx[sel];
            out[2 * N + row] = conf;

            __threadfence();
            int prev = atomicAdd(&g_done_ctr, 1);
            s_last = (prev == N - 1) ? 1 : 0;
        }
        __syncthreads();

        // last completed row: cross-row finalize (accepted flags)
        if (s_last) {
            __threadfence();
            const float thr = *thr_p;
            u64 fb = 0ull; int anyl = 0;
            float cv[4];
#pragma unroll
            for (int q = 0; q < 4; q++) {
                int r = tid + q * TPB;
                float c = (r < N) ? out[r] : -1.0f;
                cv[q] = c;
                if (r < N) {
                    if (c > thr) anyl = 1;
                    u64 k = (((u64)f2s(c)) << 32) | (u32)(N - 1 - r);
                    if (k > fb) fb = k;
                }
            }
#pragma unroll
            for (int off = 16; off; off >>= 1) {
                u64 o = __shfl_down_sync(0xffffffffu, fb, off);
                if (o > fb) fb = o;
            }
            int anyw = __any_sync(0xffffffffu, anyl);
            if (lane == 0) { s_red64[wid] = fb; s_t16[wid] = (u32)anyw; }
            __syncthreads();
            if (tid == 0) {
                u64 b = 0ull; u32 a = 0;
                for (int w = 0; w < 16; w++) {
                    if (s_red64[w] > b) b = s_red64[w];
                    a |= s_t16[w];
                }
                s_red64[0] = b;
                s_t16[0] = a;
                g_done_ctr = 0;
            }
            __syncthreads();
            const int argrow = N - 1 - (int)(u32)s_red64[0];
            const int anyh = (int)s_t16[0];
#pragma unroll
            for (int q = 0; q < 4; q++) {
                int r = tid + q * TPB;
                if (r < N)
                    out[3 * N + r] = anyh ? ((cv[q] > thr) ? 1.0f : 0.0f)
                                          : ((r == argrow) ? 1.0f : 0.0f);
            }
        }
    }
    // drain any still-pending (possibly empty) cp.async groups before exit
    asm volatile("cp.async.wait_group 0;");
}

extern "C" void kernel_launch(void* const* d_in, const int* in_sizes, int n_in,
                              void* d_out, int out_size)
{
    const float* logits = (const float*)d_in[0];
    const float* gumbel = (const float*)d_in[1];
    const float* temp   = (const float*)d_in[2];
    const float* topp   = (const float*)d_in[3];
    const int*   topk   = (const int*)  d_in[4];
    const float* thr    = (const float*)d_in[5];

    int N = in_sizes[0] / VOCAB;
    float* out = (float*)d_out;

    int G = (N < GRIDP) ? N : GRIDP;
    sampler_row_kernel<<<G, TPB>>>(logits, gumbel, temp, topp, topk, thr, out, N);
}